// round 9
// baseline (speedup 1.0000x reference)
#include <cuda_runtime.h>

// SSIM loss, B=64, 1x512x512 fp32, 11x11 box filter, zero padding.
// R8: occupancy experiment with the reg budget to back it.
//  - CHUNK=16 -> 2048 warps (512 CTAs x 128 thr), ~13.8 warps/SM demand.
//  - __launch_bounds__(128, 3) -> target <=170 regs so 3 CTAs/SM fit:
//      * enter-prefetch buffer dropped (TLP covers latency at 3 warps/SMSP)
//      * left halos on-demand per slide step (like chain B's right halos)
//      * load ordering kept: both rows' LDGs issued before first consume.
//  - keeps: paired divides, split sliding chains, f32x2 packing, rescaled
//    SSIM algebra, templated borders, last-CTA finalize.

typedef unsigned long long u64;

__device__ __forceinline__ u64 pk2(float lo, float hi) {
    u64 r; asm("mov.b64 %0, {%1, %2};" : "=l"(r) : "f"(lo), "f"(hi)); return r;
}
__device__ __forceinline__ void upk2(u64 v, float& lo, float& hi) {
    asm("mov.b64 {%0, %1}, %2;" : "=f"(lo), "=f"(hi) : "l"(v));
}
__device__ __forceinline__ u64 add2(u64 a, u64 b) {
    u64 r; asm("add.rn.f32x2 %0, %1, %2;" : "=l"(r) : "l"(a), "l"(b)); return r;
}
__device__ __forceinline__ u64 mul2(u64 a, u64 b) {
    u64 r; asm("mul.rn.f32x2 %0, %1, %2;" : "=l"(r) : "l"(a), "l"(b)); return r;
}
__device__ __forceinline__ u64 fma2(u64 a, u64 b, u64 c) {
    u64 r; asm("fma.rn.f32x2 %0, %1, %2, %3;" : "=l"(r) : "l"(a), "l"(b), "l"(c)); return r;
}

namespace {
constexpr int Hh = 512;
constexpr int Ww = 512;
constexpr int Bb = 64;
constexpr int CHUNK = 16;
constexpr int NCHUNK = Hh / CHUNK;           // 32
constexpr int BLK = 128;                     // 4 warps/CTA
constexpr int NCTA = Bb * NCHUNK * 32 / BLK; // 512
constexpr float C1S = 0.0001f * 14641.0f;    // 1.4641
constexpr float C2S = 0.0009f * 14641.0f;    // 13.1769
}

__device__ double g_acc;
__device__ int    g_count;

template<bool TOP, bool BOT>
__device__ __forceinline__ float run_chunk(const float* __restrict__ xb,
                                           const float* __restrict__ yb,
                                           const int row0, const int lane) {
    const u64 KN1 = pk2(-1.f, -1.f);
    const float lmaskf = (lane == 0)  ? 0.f : 1.f;
    const float rmaskf = (lane == 31) ? 0.f : 1.f;
    const u64 lmask2 = pk2(lmaskf, lmaskf);
    const u64 rmask2 = pk2(rmaskf, rmaskf);

    u64 vab[16], vsq[16];
    float vxy[16];
#pragma unroll
    for (int k = 0; k < 16; k++) { vab[k] = 0ull; vsq[k] = 0ull; vxy[k] = 0.f; }

    float acc = 0.f;

#define VENT(k, xs, ys) do { float _x=(xs), _y=(ys); u64 _p=pk2(_x,_y); \
    vab[k]=add2(vab[k],_p); vsq[k]=fma2(_p,_p,vsq[k]); vxy[k]=fmaf(_x,_y,vxy[k]); } while(0)
#define VLEA(k, xs, ys) do { float _x=(xs), _y=(ys); u64 _p=pk2(_x,_y); u64 _n=mul2(_p,KN1); \
    vab[k]=add2(vab[k],_n); vsq[k]=fma2(_n,_p,vsq[k]); vxy[k]=fmaf(-_x,_y,vxy[k]); } while(0)
#define ROW_APPLY(OP) \
    OP(0,a0.x,b0.x);  OP(1,a0.y,b0.y);  OP(2,a0.z,b0.z);  OP(3,a0.w,b0.w); \
    OP(4,a1.x,b1.x);  OP(5,a1.y,b1.y);  OP(6,a1.z,b1.z);  OP(7,a1.w,b1.w); \
    OP(8,a2.x,b2.x);  OP(9,a2.y,b2.y);  OP(10,a2.z,b2.z); OP(11,a2.w,b2.w); \
    OP(12,a3.x,b3.x); OP(13,a3.y,b3.y); OP(14,a3.z,b3.z); OP(15,a3.w,b3.w);

#define ENTER_DIRECT(r) do { \
    const float4* xr = reinterpret_cast<const float4*>(xb + (r) * Ww); \
    const float4* yr = reinterpret_cast<const float4*>(yb + (r) * Ww); \
    float4 a0 = xr[0], a1 = xr[1], a2 = xr[2], a3 = xr[3]; \
    float4 b0 = yr[0], b1 = yr[1], b2 = yr[2], b3 = yr[3]; \
    ROW_APPLY(VENT) } while(0)

#define SC4(v, m) do { (v).x*=(m); (v).y*=(m); (v).z*=(m); (v).w*=(m); } while(0)

    // chain A init needs left-halo sums; build from 5 on-demand shuffle triples
#define SUM11P(V) add2(add2(add2(add2(V[3],V[4]), add2(V[5],V[6])), \
                            add2(add2(V[7],V[8]), add2(V[9],V[10]))), \
                       add2(add2(V[11],V[12]), V[13]))

#define ND(sab, ssq, sxy, nv, dv) do { \
    float sx, sy, sxx, syy; \
    upk2(sab, sx, sy); \
    upk2(ssq, sxx, syy); \
    float pxy  = sx * sy; \
    float m2   = fmaf(sx, sx, sy * sy); \
    float esum = sxx + syy; \
    nv = fmaf(2.f, pxy, C1S) * fmaf(242.f, sxy, fmaf(-2.f, pxy, C2S)); \
    dv = (m2 + C1S) * fmaf(121.f, esum, C2S - m2); } while(0)

#define EPI() do { \
    /* chain A init: left halo sum (v[11..15] from lane-1) + v[0..5] */ \
    u64 hsum_ab = add2(add2(add2(vab[11], vab[12]), add2(vab[13], vab[14])), vab[15]); \
    u64 hsum_sq = add2(add2(add2(vsq[11], vsq[12]), add2(vsq[13], vsq[14])), vsq[15]); \
    float hsum_xy = ((vxy[11] + vxy[12]) + (vxy[13] + vxy[14])) + vxy[15]; \
    u64 sabA = add2(mul2(__shfl_up_sync(0xffffffffu, hsum_ab, 1), lmask2), \
                    add2(add2(add2(vab[0], vab[1]), add2(vab[2], vab[3])), add2(vab[4], vab[5]))); \
    u64 ssqA = add2(mul2(__shfl_up_sync(0xffffffffu, hsum_sq, 1), lmask2), \
                    add2(add2(add2(vsq[0], vsq[1]), add2(vsq[2], vsq[3])), add2(vsq[4], vsq[5]))); \
    float sxyA = __shfl_up_sync(0xffffffffu, hsum_xy, 1) * lmaskf \
               + (((vxy[0] + vxy[1]) + (vxy[2] + vxy[3])) + (vxy[4] + vxy[5])); \
    u64 sabB = SUM11P(vab); \
    u64 ssqB = SUM11P(vsq); \
    float sxyB = ((vxy[3]+vxy[4]) + (vxy[5]+vxy[6])) + ((vxy[7]+vxy[8]) + (vxy[9]+vxy[10])) \
               + ((vxy[11]+vxy[12]) + vxy[13]); \
    _Pragma("unroll") \
    for (int j = 0; j < 8; j++) { \
        float nA, dA, nB, dB; \
        ND(sabA, ssqA, sxyA, nA, dA); \
        ND(sabB, ssqB, sxyB, nB, dB); \
        acc += __fdividef(fmaf(nA, dB, nB * dA), dA * dB); \
        if (j < 7) { \
            /* chain A: add v[j+6]; sub on-demand left halo (j<5) / v[j-5] */ \
            sabA = add2(sabA, vab[j + 6]); \
            ssqA = add2(ssqA, vsq[j + 6]); \
            sxyA += vxy[j + 6]; \
            if (j < 5) { \
                u64 ha = mul2(__shfl_up_sync(0xffffffffu, vab[11 + j], 1), lmask2); \
                u64 hs = mul2(__shfl_up_sync(0xffffffffu, vsq[11 + j], 1), lmask2); \
                float hx = __shfl_up_sync(0xffffffffu, vxy[11 + j], 1) * lmaskf; \
                sabA = fma2(ha, KN1, sabA); \
                ssqA = fma2(hs, KN1, ssqA); \
                sxyA -= hx; \
            } else { \
                sabA = fma2(vab[j - 5], KN1, sabA); \
                ssqA = fma2(vsq[j - 5], KN1, ssqA); \
                sxyA -= vxy[j - 5]; \
            } \
            /* chain B: add v[14+j] (j<2) / on-demand right halo; sub v[j+3] */ \
            u64 hb_ab, hb_sq; \
            float hb_xy; \
            if (j < 2) { \
                hb_ab = vab[14 + j]; hb_sq = vsq[14 + j]; hb_xy = vxy[14 + j]; \
            } else { \
                hb_ab = mul2(__shfl_down_sync(0xffffffffu, vab[j - 2], 1), rmask2); \
                hb_sq = mul2(__shfl_down_sync(0xffffffffu, vsq[j - 2], 1), rmask2); \
                hb_xy = __shfl_down_sync(0xffffffffu, vxy[j - 2], 1) * rmaskf; \
            } \
            sabB = add2(sabB, hb_ab); \
            sabB = fma2(vab[j + 3], KN1, sabB); \
            ssqB = add2(ssqB, hb_sq); \
            ssqB = fma2(vsq[j + 3], KN1, ssqB); \
            sxyB += hb_xy - vxy[j + 3]; \
        } \
    } } while(0)

    // ---- warmup: rows row0-5 .. row0+4 (TOP skips negative rows) ----
    {
        const int w0 = TOP ? 5 : 0;
#pragma unroll
        for (int i = w0; i < 10; i++) ENTER_DIRECT(row0 - 5 + i);
    }

    // ---- first output row (ri = row0+5, no leave) ----
    ENTER_DIRECT(row0 + 5);
    EPI();

    // ---- steady: CHUNK-1 iterations; leave+enter loads issued up front ----
#pragma unroll 1
    for (int i = 0; i < CHUNK - 1; i++) {
        const int ri = row0 + 6 + i;
        const int lv = ri - 11;
        // issue leave-row loads first
        float4 la0, la1, la2, la3, lb0, lb1, lb2, lb3;
        {
            const int lr = TOP ? ((lv < 0) ? 0 : lv) : lv;
            const float4* _xr = reinterpret_cast<const float4*>(xb + lr * Ww);
            const float4* _yr = reinterpret_cast<const float4*>(yb + lr * Ww);
            la0 = _xr[0]; la1 = _xr[1]; la2 = _xr[2]; la3 = _xr[3];
            lb0 = _yr[0]; lb1 = _yr[1]; lb2 = _yr[2]; lb3 = _yr[3];
        }
        {   // enter row: load + consume (loads issue before consume ops)
            const int er = BOT ? ((ri > Hh - 1) ? Hh - 1 : ri) : ri;
            const float4* _xr = reinterpret_cast<const float4*>(xb + er * Ww);
            const float4* _yr = reinterpret_cast<const float4*>(yb + er * Ww);
            float4 a0 = _xr[0], a1 = _xr[1], a2 = _xr[2], a3 = _xr[3];
            float4 b0 = _yr[0], b1 = _yr[1], b2 = _yr[2], b3 = _yr[3];
            if (BOT) {
                const float em = (ri < Hh) ? 1.f : 0.f;
                SC4(a0, em); SC4(a1, em); SC4(a2, em); SC4(a3, em);
                SC4(b0, em); SC4(b1, em); SC4(b2, em); SC4(b3, em);
            }
            ROW_APPLY(VENT)
        }
        {   // consume leave
            float4 a0 = la0, a1 = la1, a2 = la2, a3 = la3;
            float4 b0 = lb0, b1 = lb1, b2 = lb2, b3 = lb3;
            if (TOP) {
                const float lm = (lv >= 0) ? 1.f : 0.f;
                SC4(a0, lm); SC4(a1, lm); SC4(a2, lm); SC4(a3, lm);
                SC4(b0, lm); SC4(b1, lm); SC4(b2, lm); SC4(b3, lm);
            }
            ROW_APPLY(VLEA)
        }
        EPI();
    }

    return acc;

#undef VENT
#undef VLEA
#undef ROW_APPLY
#undef ENTER_DIRECT
#undef SC4
#undef SUM11P
#undef ND
#undef EPI
}

__global__ void __launch_bounds__(BLK, 3)
k_ssim(const float* __restrict__ X, const float* __restrict__ Y, float* __restrict__ out) {
    const int warp  = threadIdx.x >> 5;
    const int lane  = threadIdx.x & 31;
    const int gwarp = blockIdx.x * (BLK / 32) + warp;
    const int batch = gwarp >> 5;              // / NCHUNK (=32)
    const int chunk = gwarp & (NCHUNK - 1);
    const int row0  = chunk * CHUNK;
    const int c0    = lane << 4;
    const float* xb = X + batch * (Hh * Ww) + c0;
    const float* yb = Y + batch * (Hh * Ww) + c0;

    __shared__ float s_red[BLK / 32];

    float acc;
    if (chunk == 0)                acc = run_chunk<true,  false>(xb, yb, 0, lane);
    else if (chunk == NCHUNK - 1)  acc = run_chunk<false, true >(xb, yb, row0, lane);
    else                           acc = run_chunk<false, false>(xb, yb, row0, lane);

#pragma unroll
    for (int off = 16; off; off >>= 1)
        acc += __shfl_xor_sync(0xffffffffu, acc, off);
    if (lane == 0) s_red[warp] = acc;
    __syncthreads();
    if (threadIdx.x == 0) {
        float ctot = 0.f;
#pragma unroll
        for (int w = 0; w < BLK / 32; w++) ctot += s_red[w];
        atomicAdd(&g_acc, (double)ctot);
        __threadfence();
        int old = atomicAdd(&g_count, 1);
        if (old == NCTA - 1) {
            double total = g_acc;
            out[0] = (float)(1.0 - total * (1.0 / ((double)Bb * Hh * Ww)));
            g_acc = 0.0;
            g_count = 0;
        }
    }
}

extern "C" void kernel_launch(void* const* d_in, const int* in_sizes, int n_in,
                              void* d_out, int out_size) {
    const float* x = (const float*)d_in[0];
    const float* y = (const float*)d_in[1];
    (void)in_sizes; (void)n_in; (void)out_size;
    k_ssim<<<NCTA, BLK>>>(x, y, (float*)d_out);
}

// round 10
// speedup vs baseline: 1.7426x; 1.7426x over previous
#include <cuda_runtime.h>
#include <cstdint>

// SSIM loss, B=64, 1x512x512 fp32, 11x11 box filter, zero padding.
// R9: coalesced cp.async staging. R7's loads were 4x uncoalesced
// (lane stride 64B -> nL=16 lines/LDG; wavefront math matches ncu's 55% L1).
//  - per-warp smem row buffers, XOR-swizzled (j ^ ((j>>3)&7)): coalesced
//    16B/lane cp.async.cg writes + conflict-free blocked 64B/lane reads.
//  - stage-ahead-by-one: next row-pair staged during current epilogue
//    (async, register-free) -> no prefetch regs, no exposed STS stall.
//  - frame: CHUNK=32, 256 CTAs x 128 thr (locked: 3 experiments show more
//    warps regress), R8 reg-lean epilogue, paired divides, split chains.

typedef unsigned long long u64;

__device__ __forceinline__ u64 pk2(float lo, float hi) {
    u64 r; asm("mov.b64 %0, {%1, %2};" : "=l"(r) : "f"(lo), "f"(hi)); return r;
}
__device__ __forceinline__ void upk2(u64 v, float& lo, float& hi) {
    asm("mov.b64 {%0, %1}, %2;" : "=f"(lo), "=f"(hi) : "l"(v));
}
__device__ __forceinline__ u64 add2(u64 a, u64 b) {
    u64 r; asm("add.rn.f32x2 %0, %1, %2;" : "=l"(r) : "l"(a), "l"(b)); return r;
}
__device__ __forceinline__ u64 mul2(u64 a, u64 b) {
    u64 r; asm("mul.rn.f32x2 %0, %1, %2;" : "=l"(r) : "l"(a), "l"(b)); return r;
}
__device__ __forceinline__ u64 fma2(u64 a, u64 b, u64 c) {
    u64 r; asm("fma.rn.f32x2 %0, %1, %2, %3;" : "=l"(r) : "l"(a), "l"(b), "l"(c)); return r;
}
__device__ __forceinline__ void cp16(uint32_t dst, const void* src) {
    asm volatile("cp.async.cg.shared.global [%0], [%1], 16;" :: "r"(dst), "l"(src));
}
__device__ __forceinline__ void cp_commit() {
    asm volatile("cp.async.commit_group;" ::: "memory");
}
__device__ __forceinline__ void cp_wait0() {
    asm volatile("cp.async.wait_group 0;" ::: "memory");
}
__device__ __forceinline__ int swz(int j) { return j ^ ((j >> 3) & 7); }

namespace {
constexpr int Hh = 512;
constexpr int Ww = 512;
constexpr int Bb = 64;
constexpr int CHUNK = 32;
constexpr int NCHUNK = Hh / CHUNK;           // 16
constexpr int BLK = 128;                     // 4 warps/CTA
constexpr int NCTA = Bb * NCHUNK * 32 / BLK; // 256
constexpr float C1S = 0.0001f * 14641.0f;    // 1.4641
constexpr float C2S = 0.0009f * 14641.0f;    // 13.1769
}

__device__ double g_acc;
__device__ int    g_count;

// per-warp staging: 4 bufs (enter-x, enter-y, leave-x, leave-y) x 128 float4
// total 4 warps * 4 * 128 * 16B = 32 KB static smem

template<bool TOP, bool BOT>
__device__ __forceinline__ float run_chunk(const float* __restrict__ xw,
                                           const float* __restrict__ yw,
                                           const int row0, const int lane,
                                           float4 (*sb)[128]) {
    const u64 KN1 = pk2(-1.f, -1.f);
    const float lmaskf = (lane == 0)  ? 0.f : 1.f;
    const float rmaskf = (lane == 31) ? 0.f : 1.f;
    const u64 lmask2 = pk2(lmaskf, lmaskf);
    const u64 rmask2 = pk2(rmaskf, rmaskf);
    const int c0 = lane << 4;

    u64 vab[16], vsq[16];
    float vxy[16];
#pragma unroll
    for (int k = 0; k < 16; k++) { vab[k] = 0ull; vsq[k] = 0ull; vxy[k] = 0.f; }

    float acc = 0.f;

    // cp.async dst addresses for this lane's 4 words per buffer
    uint32_t dst[4][4];
#pragma unroll
    for (int b = 0; b < 4; b++)
#pragma unroll
        for (int q = 0; q < 4; q++)
            dst[b][q] = (uint32_t)__cvta_generic_to_shared(&sb[b][swz(lane + 32 * q)]);

#define VENT(k, xs, ys) do { float _x=(xs), _y=(ys); u64 _p=pk2(_x,_y); \
    vab[k]=add2(vab[k],_p); vsq[k]=fma2(_p,_p,vsq[k]); vxy[k]=fmaf(_x,_y,vxy[k]); } while(0)
#define VLEA(k, xs, ys) do { float _x=(xs), _y=(ys); u64 _p=pk2(_x,_y); u64 _n=mul2(_p,KN1); \
    vab[k]=add2(vab[k],_n); vsq[k]=fma2(_n,_p,vsq[k]); vxy[k]=fmaf(-_x,_y,vxy[k]); } while(0)
#define ROW_APPLY(OP) \
    OP(0,a0.x,b0.x);  OP(1,a0.y,b0.y);  OP(2,a0.z,b0.z);  OP(3,a0.w,b0.w); \
    OP(4,a1.x,b1.x);  OP(5,a1.y,b1.y);  OP(6,a1.z,b1.z);  OP(7,a1.w,b1.w); \
    OP(8,a2.x,b2.x);  OP(9,a2.y,b2.y);  OP(10,a2.z,b2.z); OP(11,a2.w,b2.w); \
    OP(12,a3.x,b3.x); OP(13,a3.y,b3.y); OP(14,a3.z,b3.z); OP(15,a3.w,b3.w);

#define ENTER_DIRECT(r) do { \
    const float4* xr = reinterpret_cast<const float4*>(xw + (r) * Ww + c0); \
    const float4* yr = reinterpret_cast<const float4*>(yw + (r) * Ww + c0); \
    float4 a0 = xr[0], a1 = xr[1], a2 = xr[2], a3 = xr[3]; \
    float4 b0 = yr[0], b1 = yr[1], b2 = yr[2], b3 = yr[3]; \
    ROW_APPLY(VENT) } while(0)

    // stage enter row er + leave row lr (coalesced, async)
#define STAGE(er, lr) do { \
    const float* _ex = xw + (er) * Ww; \
    const float* _ey = yw + (er) * Ww; \
    const float* _lx = xw + (lr) * Ww; \
    const float* _ly = yw + (lr) * Ww; \
    _Pragma("unroll") \
    for (int q = 0; q < 4; q++) { \
        const int w4 = (lane + 32 * q) * 4; \
        cp16(dst[0][q], _ex + w4); \
        cp16(dst[1][q], _ey + w4); \
        cp16(dst[2][q], _lx + w4); \
        cp16(dst[3][q], _ly + w4); \
    } \
    cp_commit(); } while(0)

#define SC4(v, m) do { (v).x*=(m); (v).y*=(m); (v).z*=(m); (v).w*=(m); } while(0)

#define SUM11P(V) add2(add2(add2(add2(V[3],V[4]), add2(V[5],V[6])), \
                            add2(add2(V[7],V[8]), add2(V[9],V[10]))), \
                       add2(add2(V[11],V[12]), V[13]))

#define ND(sab, ssq, sxy, nv, dv) do { \
    float sx, sy, sxx, syy; \
    upk2(sab, sx, sy); \
    upk2(ssq, sxx, syy); \
    float pxy  = sx * sy; \
    float m2   = fmaf(sx, sx, sy * sy); \
    float esum = sxx + syy; \
    nv = fmaf(2.f, pxy, C1S) * fmaf(242.f, sxy, fmaf(-2.f, pxy, C2S)); \
    dv = (m2 + C1S) * fmaf(121.f, esum, C2S - m2); } while(0)

#define EPI() do { \
    u64 hsum_ab = add2(add2(add2(vab[11], vab[12]), add2(vab[13], vab[14])), vab[15]); \
    u64 hsum_sq = add2(add2(add2(vsq[11], vsq[12]), add2(vsq[13], vsq[14])), vsq[15]); \
    float hsum_xy = ((vxy[11] + vxy[12]) + (vxy[13] + vxy[14])) + vxy[15]; \
    u64 sabA = add2(mul2(__shfl_up_sync(0xffffffffu, hsum_ab, 1), lmask2), \
                    add2(add2(add2(vab[0], vab[1]), add2(vab[2], vab[3])), add2(vab[4], vab[5]))); \
    u64 ssqA = add2(mul2(__shfl_up_sync(0xffffffffu, hsum_sq, 1), lmask2), \
                    add2(add2(add2(vsq[0], vsq[1]), add2(vsq[2], vsq[3])), add2(vsq[4], vsq[5]))); \
    float sxyA = __shfl_up_sync(0xffffffffu, hsum_xy, 1) * lmaskf \
               + (((vxy[0] + vxy[1]) + (vxy[2] + vxy[3])) + (vxy[4] + vxy[5])); \
    u64 sabB = SUM11P(vab); \
    u64 ssqB = SUM11P(vsq); \
    float sxyB = ((vxy[3]+vxy[4]) + (vxy[5]+vxy[6])) + ((vxy[7]+vxy[8]) + (vxy[9]+vxy[10])) \
               + ((vxy[11]+vxy[12]) + vxy[13]); \
    _Pragma("unroll") \
    for (int j = 0; j < 8; j++) { \
        float nA, dA, nB, dB; \
        ND(sabA, ssqA, sxyA, nA, dA); \
        ND(sabB, ssqB, sxyB, nB, dB); \
        acc += __fdividef(fmaf(nA, dB, nB * dA), dA * dB); \
        if (j < 7) { \
            sabA = add2(sabA, vab[j + 6]); \
            ssqA = add2(ssqA, vsq[j + 6]); \
            sxyA += vxy[j + 6]; \
            if (j < 5) { \
                u64 ha = mul2(__shfl_up_sync(0xffffffffu, vab[11 + j], 1), lmask2); \
                u64 hs = mul2(__shfl_up_sync(0xffffffffu, vsq[11 + j], 1), lmask2); \
                float hx = __shfl_up_sync(0xffffffffu, vxy[11 + j], 1) * lmaskf; \
                sabA = fma2(ha, KN1, sabA); \
                ssqA = fma2(hs, KN1, ssqA); \
                sxyA -= hx; \
            } else { \
                sabA = fma2(vab[j - 5], KN1, sabA); \
                ssqA = fma2(vsq[j - 5], KN1, ssqA); \
                sxyA -= vxy[j - 5]; \
            } \
            u64 hb_ab, hb_sq; \
            float hb_xy; \
            if (j < 2) { \
                hb_ab = vab[14 + j]; hb_sq = vsq[14 + j]; hb_xy = vxy[14 + j]; \
            } else { \
                hb_ab = mul2(__shfl_down_sync(0xffffffffu, vab[j - 2], 1), rmask2); \
                hb_sq = mul2(__shfl_down_sync(0xffffffffu, vsq[j - 2], 1), rmask2); \
                hb_xy = __shfl_down_sync(0xffffffffu, vxy[j - 2], 1) * rmaskf; \
            } \
            sabB = add2(sabB, hb_ab); \
            sabB = fma2(vab[j + 3], KN1, sabB); \
            ssqB = add2(ssqB, hb_sq); \
            ssqB = fma2(vsq[j + 3], KN1, ssqB); \
            sxyB += hb_xy - vxy[j + 3]; \
        } \
    } } while(0)

    // ---- warmup: rows row0-5 .. row0+4 (direct loads; 11 of 77 visits) ----
    {
        const int w0 = TOP ? 5 : 0;
#pragma unroll
        for (int i = w0; i < 10; i++) ENTER_DIRECT(row0 - 5 + i);
    }

    // ---- first output row (ri = row0+5, no leave) ----
    ENTER_DIRECT(row0 + 5);
    {   // stage iter-0 rows: enter row0+6, leave row0-5 (clamped, masked later)
        const int er = row0 + 6;                                 // < Hh always
        const int lr = TOP ? 0 : (row0 - 5);
        STAGE(er, lr);
    }
    EPI();

    // ---- steady: 31 iterations ----
#pragma unroll 1
    for (int i = 0; i < CHUNK - 1; i++) {
        const int ri = row0 + 6 + i;
        const int lv = ri - 11;
        cp_wait0();
        __syncwarp();
        {   // consume enter
            float4 a0 = sb[0][swz(4*lane+0)], a1 = sb[0][swz(4*lane+1)],
                   a2 = sb[0][swz(4*lane+2)], a3 = sb[0][swz(4*lane+3)];
            float4 b0 = sb[1][swz(4*lane+0)], b1 = sb[1][swz(4*lane+1)],
                   b2 = sb[1][swz(4*lane+2)], b3 = sb[1][swz(4*lane+3)];
            if (BOT) {
                const float em = (ri < Hh) ? 1.f : 0.f;
                SC4(a0, em); SC4(a1, em); SC4(a2, em); SC4(a3, em);
                SC4(b0, em); SC4(b1, em); SC4(b2, em); SC4(b3, em);
            }
            ROW_APPLY(VENT)
        }
        {   // consume leave
            float4 a0 = sb[2][swz(4*lane+0)], a1 = sb[2][swz(4*lane+1)],
                   a2 = sb[2][swz(4*lane+2)], a3 = sb[2][swz(4*lane+3)];
            float4 b0 = sb[3][swz(4*lane+0)], b1 = sb[3][swz(4*lane+1)],
                   b2 = sb[3][swz(4*lane+2)], b3 = sb[3][swz(4*lane+3)];
            if (TOP) {
                const float lm = (lv >= 0) ? 1.f : 0.f;
                SC4(a0, lm); SC4(a1, lm); SC4(a2, lm); SC4(a3, lm);
                SC4(b0, lm); SC4(b1, lm); SC4(b2, lm); SC4(b3, lm);
            }
            ROW_APPLY(VLEA)
        }
        __syncwarp();
        if (i < CHUNK - 2) {   // stage next iteration's rows (hidden under EPI)
            int er = ri + 1; if (BOT && er > Hh - 1) er = Hh - 1;
            int lr = lv + 1; if (TOP && lr < 0) lr = 0;
            STAGE(er, lr);
        }
        EPI();
    }

    return acc;

#undef VENT
#undef VLEA
#undef ROW_APPLY
#undef ENTER_DIRECT
#undef STAGE
#undef SC4
#undef SUM11P
#undef ND
#undef EPI
}

__global__ void __launch_bounds__(BLK)
k_ssim(const float* __restrict__ X, const float* __restrict__ Y, float* __restrict__ out) {
    const int warp  = threadIdx.x >> 5;
    const int lane  = threadIdx.x & 31;
    const int gwarp = blockIdx.x * (BLK / 32) + warp;
    const int batch = gwarp >> 4;              // / NCHUNK
    const int chunk = gwarp & (NCHUNK - 1);
    const int row0  = chunk * CHUNK;
    const float* xw = X + batch * (Hh * Ww);
    const float* yw = Y + batch * (Hh * Ww);

    __shared__ float4 sstage[BLK / 32][4][128];   // 32 KB
    __shared__ float  s_red[BLK / 32];

    float acc;
    if (chunk == 0)                acc = run_chunk<true,  false>(xw, yw, 0,    lane, sstage[warp]);
    else if (chunk == NCHUNK - 1)  acc = run_chunk<false, true >(xw, yw, row0, lane, sstage[warp]);
    else                           acc = run_chunk<false, false>(xw, yw, row0, lane, sstage[warp]);

#pragma unroll
    for (int off = 16; off; off >>= 1)
        acc += __shfl_xor_sync(0xffffffffu, acc, off);
    if (lane == 0) s_red[warp] = acc;
    __syncthreads();
    if (threadIdx.x == 0) {
        float ctot = 0.f;
#pragma unroll
        for (int w = 0; w < BLK / 32; w++) ctot += s_red[w];
        atomicAdd(&g_acc, (double)ctot);
        __threadfence();
        int old = atomicAdd(&g_count, 1);
        if (old == NCTA - 1) {
            double total = g_acc;
            out[0] = (float)(1.0 - total * (1.0 / ((double)Bb * Hh * Ww)));
            g_acc = 0.0;
            g_count = 0;
        }
    }
}

extern "C" void kernel_launch(void* const* d_in, const int* in_sizes, int n_in,
                              void* d_out, int out_size) {
    const float* x = (const float*)d_in[0];
    const float* y = (const float*)d_in[1];
    (void)in_sizes; (void)n_in; (void)out_size;
    k_ssim<<<NCTA, BLK>>>(x, y, (float*)d_out);
}

// round 11
// speedup vs baseline: 1.7437x; 1.0006x over previous
#include <cuda_runtime.h>
#include <cstdint>

// SSIM loss, B=64, 1x512x512 fp32, 11x11 box filter, zero padding.
// R10: depth-2 cp.async pipeline (R9's single buffer exposed ~200cyc of
// first-touch DRAM latency per iteration at wait_group 0).
//  - two stage buffers/warp; rows for iter i+2 staged during iter i
//    (~2 iterations ~900cyc of cover > 577cyc DRAM).
//  - wait_group 1: never wait on the newest in-flight group.
//  - uniform accounting: every iteration stages exactly one (clamped) group.
// Frozen: CHUNK=32, 256 CTAs x 128 thr, reg-lean epilogue w/ on-demand halos,
// paired divides, split sliding chains, f32x2 packing, last-CTA finalize.

typedef unsigned long long u64;

__device__ __forceinline__ u64 pk2(float lo, float hi) {
    u64 r; asm("mov.b64 %0, {%1, %2};" : "=l"(r) : "f"(lo), "f"(hi)); return r;
}
__device__ __forceinline__ void upk2(u64 v, float& lo, float& hi) {
    asm("mov.b64 {%0, %1}, %2;" : "=f"(lo), "=f"(hi) : "l"(v));
}
__device__ __forceinline__ u64 add2(u64 a, u64 b) {
    u64 r; asm("add.rn.f32x2 %0, %1, %2;" : "=l"(r) : "l"(a), "l"(b)); return r;
}
__device__ __forceinline__ u64 mul2(u64 a, u64 b) {
    u64 r; asm("mul.rn.f32x2 %0, %1, %2;" : "=l"(r) : "l"(a), "l"(b)); return r;
}
__device__ __forceinline__ u64 fma2(u64 a, u64 b, u64 c) {
    u64 r; asm("fma.rn.f32x2 %0, %1, %2, %3;" : "=l"(r) : "l"(a), "l"(b), "l"(c)); return r;
}
__device__ __forceinline__ void cp16(uint32_t dst, const void* src) {
    asm volatile("cp.async.cg.shared.global [%0], [%1], 16;" :: "r"(dst), "l"(src));
}
__device__ __forceinline__ void cp_commit() {
    asm volatile("cp.async.commit_group;" ::: "memory");
}
__device__ __forceinline__ void cp_wait1() {
    asm volatile("cp.async.wait_group 1;" ::: "memory");
}
__device__ __forceinline__ int swz(int j) { return j ^ ((j >> 3) & 7); }

namespace {
constexpr int Hh = 512;
constexpr int Ww = 512;
constexpr int Bb = 64;
constexpr int CHUNK = 32;
constexpr int NCHUNK = Hh / CHUNK;           // 16
constexpr int BLK = 128;                     // 4 warps/CTA
constexpr int NCTA = Bb * NCHUNK * 32 / BLK; // 256
constexpr float C1S = 0.0001f * 14641.0f;    // 1.4641
constexpr float C2S = 0.0009f * 14641.0f;    // 13.1769
constexpr int STAGE_BYTES = 4 * 128 * 16;    // one stage: 4 bufs x 128 float4
}

__device__ double g_acc;
__device__ int    g_count;

template<bool TOP, bool BOT>
__device__ __forceinline__ float run_chunk(const float* __restrict__ xw,
                                           const float* __restrict__ yw,
                                           const int row0, const int lane,
                                           float4 (*sb)[4][128]) {
    const u64 KN1 = pk2(-1.f, -1.f);
    const float lmaskf = (lane == 0)  ? 0.f : 1.f;
    const float rmaskf = (lane == 31) ? 0.f : 1.f;
    const u64 lmask2 = pk2(lmaskf, lmaskf);
    const u64 rmask2 = pk2(rmaskf, rmaskf);
    const int c0 = lane << 4;

    u64 vab[16], vsq[16];
    float vxy[16];
#pragma unroll
    for (int k = 0; k < 16; k++) { vab[k] = 0ull; vsq[k] = 0ull; vxy[k] = 0.f; }

    float acc = 0.f;

    // cp.async dst addresses (stage 0); stage 1 = +STAGE_BYTES
    uint32_t dst[4][4];
#pragma unroll
    for (int b = 0; b < 4; b++)
#pragma unroll
        for (int q = 0; q < 4; q++)
            dst[b][q] = (uint32_t)__cvta_generic_to_shared(&sb[0][b][swz(lane + 32 * q)]);

#define VENT(k, xs, ys) do { float _x=(xs), _y=(ys); u64 _p=pk2(_x,_y); \
    vab[k]=add2(vab[k],_p); vsq[k]=fma2(_p,_p,vsq[k]); vxy[k]=fmaf(_x,_y,vxy[k]); } while(0)
#define VLEA(k, xs, ys) do { float _x=(xs), _y=(ys); u64 _p=pk2(_x,_y); u64 _n=mul2(_p,KN1); \
    vab[k]=add2(vab[k],_n); vsq[k]=fma2(_n,_p,vsq[k]); vxy[k]=fmaf(-_x,_y,vxy[k]); } while(0)
#define ROW_APPLY(OP) \
    OP(0,a0.x,b0.x);  OP(1,a0.y,b0.y);  OP(2,a0.z,b0.z);  OP(3,a0.w,b0.w); \
    OP(4,a1.x,b1.x);  OP(5,a1.y,b1.y);  OP(6,a1.z,b1.z);  OP(7,a1.w,b1.w); \
    OP(8,a2.x,b2.x);  OP(9,a2.y,b2.y);  OP(10,a2.z,b2.z); OP(11,a2.w,b2.w); \
    OP(12,a3.x,b3.x); OP(13,a3.y,b3.y); OP(14,a3.z,b3.z); OP(15,a3.w,b3.w);

#define ENTER_DIRECT(r) do { \
    const float4* xr = reinterpret_cast<const float4*>(xw + (r) * Ww + c0); \
    const float4* yr = reinterpret_cast<const float4*>(yw + (r) * Ww + c0); \
    float4 a0 = xr[0], a1 = xr[1], a2 = xr[2], a3 = xr[3]; \
    float4 b0 = yr[0], b1 = yr[1], b2 = yr[2], b3 = yr[3]; \
    ROW_APPLY(VENT) } while(0)

    // stage enter row er + leave row lr into stage s (coalesced, async)
#define STAGE(s, er, lr) do { \
    const uint32_t _off = (uint32_t)(s) * STAGE_BYTES; \
    const float* _ex = xw + (er) * Ww; \
    const float* _ey = yw + (er) * Ww; \
    const float* _lx = xw + (lr) * Ww; \
    const float* _ly = yw + (lr) * Ww; \
    _Pragma("unroll") \
    for (int q = 0; q < 4; q++) { \
        const int w4 = (lane + 32 * q) * 4; \
        cp16(dst[0][q] + _off, _ex + w4); \
        cp16(dst[1][q] + _off, _ey + w4); \
        cp16(dst[2][q] + _off, _lx + w4); \
        cp16(dst[3][q] + _off, _ly + w4); \
    } \
    cp_commit(); } while(0)

#define SC4(v, m) do { (v).x*=(m); (v).y*=(m); (v).z*=(m); (v).w*=(m); } while(0)

#define SUM11P(V) add2(add2(add2(add2(V[3],V[4]), add2(V[5],V[6])), \
                            add2(add2(V[7],V[8]), add2(V[9],V[10]))), \
                       add2(add2(V[11],V[12]), V[13]))

#define ND(sab, ssq, sxy, nv, dv) do { \
    float sx, sy, sxx, syy; \
    upk2(sab, sx, sy); \
    upk2(ssq, sxx, syy); \
    float pxy  = sx * sy; \
    float m2   = fmaf(sx, sx, sy * sy); \
    float esum = sxx + syy; \
    nv = fmaf(2.f, pxy, C1S) * fmaf(242.f, sxy, fmaf(-2.f, pxy, C2S)); \
    dv = (m2 + C1S) * fmaf(121.f, esum, C2S - m2); } while(0)

#define EPI() do { \
    u64 hsum_ab = add2(add2(add2(vab[11], vab[12]), add2(vab[13], vab[14])), vab[15]); \
    u64 hsum_sq = add2(add2(add2(vsq[11], vsq[12]), add2(vsq[13], vsq[14])), vsq[15]); \
    float hsum_xy = ((vxy[11] + vxy[12]) + (vxy[13] + vxy[14])) + vxy[15]; \
    u64 sabA = add2(mul2(__shfl_up_sync(0xffffffffu, hsum_ab, 1), lmask2), \
                    add2(add2(add2(vab[0], vab[1]), add2(vab[2], vab[3])), add2(vab[4], vab[5]))); \
    u64 ssqA = add2(mul2(__shfl_up_sync(0xffffffffu, hsum_sq, 1), lmask2), \
                    add2(add2(add2(vsq[0], vsq[1]), add2(vsq[2], vsq[3])), add2(vsq[4], vsq[5]))); \
    float sxyA = __shfl_up_sync(0xffffffffu, hsum_xy, 1) * lmaskf \
               + (((vxy[0] + vxy[1]) + (vxy[2] + vxy[3])) + (vxy[4] + vxy[5])); \
    u64 sabB = SUM11P(vab); \
    u64 ssqB = SUM11P(vsq); \
    float sxyB = ((vxy[3]+vxy[4]) + (vxy[5]+vxy[6])) + ((vxy[7]+vxy[8]) + (vxy[9]+vxy[10])) \
               + ((vxy[11]+vxy[12]) + vxy[13]); \
    _Pragma("unroll") \
    for (int j = 0; j < 8; j++) { \
        float nA, dA, nB, dB; \
        ND(sabA, ssqA, sxyA, nA, dA); \
        ND(sabB, ssqB, sxyB, nB, dB); \
        acc += __fdividef(fmaf(nA, dB, nB * dA), dA * dB); \
        if (j < 7) { \
            sabA = add2(sabA, vab[j + 6]); \
            ssqA = add2(ssqA, vsq[j + 6]); \
            sxyA += vxy[j + 6]; \
            if (j < 5) { \
                u64 ha = mul2(__shfl_up_sync(0xffffffffu, vab[11 + j], 1), lmask2); \
                u64 hs = mul2(__shfl_up_sync(0xffffffffu, vsq[11 + j], 1), lmask2); \
                float hx = __shfl_up_sync(0xffffffffu, vxy[11 + j], 1) * lmaskf; \
                sabA = fma2(ha, KN1, sabA); \
                ssqA = fma2(hs, KN1, ssqA); \
                sxyA -= hx; \
            } else { \
                sabA = fma2(vab[j - 5], KN1, sabA); \
                ssqA = fma2(vsq[j - 5], KN1, ssqA); \
                sxyA -= vxy[j - 5]; \
            } \
            u64 hb_ab, hb_sq; \
            float hb_xy; \
            if (j < 2) { \
                hb_ab = vab[14 + j]; hb_sq = vsq[14 + j]; hb_xy = vxy[14 + j]; \
            } else { \
                hb_ab = mul2(__shfl_down_sync(0xffffffffu, vab[j - 2], 1), rmask2); \
                hb_sq = mul2(__shfl_down_sync(0xffffffffu, vsq[j - 2], 1), rmask2); \
                hb_xy = __shfl_down_sync(0xffffffffu, vxy[j - 2], 1) * rmaskf; \
            } \
            sabB = add2(sabB, hb_ab); \
            sabB = fma2(vab[j + 3], KN1, sabB); \
            ssqB = add2(ssqB, hb_sq); \
            ssqB = fma2(vsq[j + 3], KN1, ssqB); \
            sxyB += hb_xy - vxy[j + 3]; \
        } \
    } } while(0)

    // clamped staging row indices for iteration k (k = 0 .. CHUNK-2 real,
    // k up to CHUNK for dummy stages; garbage never consumed)
#define ER_OF(k) (BOT ? (((row0 + 6 + (k)) > Hh - 1) ? (Hh - 1) : (row0 + 6 + (k))) : (row0 + 6 + (k)))
#define LR_OF(k) (TOP ? (((row0 - 5 + (k)) < 0) ? 0 : (row0 - 5 + (k))) : (row0 - 5 + (k)))

    // ---- warmup: rows row0-5 .. row0+4 (direct loads) ----
    {
        const int w0 = TOP ? 5 : 0;
#pragma unroll
        for (int i = w0; i < 10; i++) ENTER_DIRECT(row0 - 5 + i);
    }

    // ---- first output row (ri = row0+5, no leave) ----
    ENTER_DIRECT(row0 + 5);
    STAGE(0, ER_OF(0), LR_OF(0));   // iter 0 rows
    STAGE(1, ER_OF(1), LR_OF(1));   // iter 1 rows
    EPI();

    // ---- steady: 31 iterations, depth-2 pipeline ----
#pragma unroll 1
    for (int i = 0; i < CHUNK - 1; i++) {
        const int ri = row0 + 6 + i;
        const int lv = ri - 11;
        const int s  = i & 1;
        cp_wait1();                  // group for iter i is complete
        {   // consume enter
            float4 a0 = sb[s][0][swz(4*lane+0)], a1 = sb[s][0][swz(4*lane+1)],
                   a2 = sb[s][0][swz(4*lane+2)], a3 = sb[s][0][swz(4*lane+3)];
            float4 b0 = sb[s][1][swz(4*lane+0)], b1 = sb[s][1][swz(4*lane+1)],
                   b2 = sb[s][1][swz(4*lane+2)], b3 = sb[s][1][swz(4*lane+3)];
            if (BOT) {
                const float em = (ri < Hh) ? 1.f : 0.f;
                SC4(a0, em); SC4(a1, em); SC4(a2, em); SC4(a3, em);
                SC4(b0, em); SC4(b1, em); SC4(b2, em); SC4(b3, em);
            }
            ROW_APPLY(VENT)
        }
        {   // consume leave
            float4 a0 = sb[s][2][swz(4*lane+0)], a1 = sb[s][2][swz(4*lane+1)],
                   a2 = sb[s][2][swz(4*lane+2)], a3 = sb[s][2][swz(4*lane+3)];
            float4 b0 = sb[s][3][swz(4*lane+0)], b1 = sb[s][3][swz(4*lane+1)],
                   b2 = sb[s][3][swz(4*lane+2)], b3 = sb[s][3][swz(4*lane+3)];
            if (TOP) {
                const float lm = (lv >= 0) ? 1.f : 0.f;
                SC4(a0, lm); SC4(a1, lm); SC4(a2, lm); SC4(a3, lm);
                SC4(b0, lm); SC4(b1, lm); SC4(b2, lm); SC4(b3, lm);
            }
            ROW_APPLY(VLEA)
        }
        __syncwarp();                // WAR guard before restaging this buffer
        {   // stage iter i+2 rows (clamped; dummies past the end never consumed)
            const int k2 = (i + 2 <= CHUNK) ? (i + 2) : CHUNK;
            STAGE(s, ER_OF(k2), LR_OF(k2));
        }
        EPI();
    }

    return acc;

#undef VENT
#undef VLEA
#undef ROW_APPLY
#undef ENTER_DIRECT
#undef STAGE
#undef SC4
#undef SUM11P
#undef ND
#undef EPI
#undef ER_OF
#undef LR_OF
}

__global__ void __launch_bounds__(BLK)
k_ssim(const float* __restrict__ X, const float* __restrict__ Y, float* __restrict__ out) {
    const int warp  = threadIdx.x >> 5;
    const int lane  = threadIdx.x & 31;
    const int gwarp = blockIdx.x * (BLK / 32) + warp;
    const int batch = gwarp >> 4;              // / NCHUNK
    const int chunk = gwarp & (NCHUNK - 1);
    const int row0  = chunk * CHUNK;
    const float* xw = X + batch * (Hh * Ww);
    const float* yw = Y + batch * (Hh * Ww);

    __shared__ float4 sstage[BLK / 32][2][4][128];   // 64 KB
    __shared__ float  s_red[BLK / 32];

    float acc;
    if (chunk == 0)                acc = run_chunk<true,  false>(xw, yw, 0,    lane, sstage[warp]);
    else if (chunk == NCHUNK - 1)  acc = run_chunk<false, true >(xw, yw, row0, lane, sstage[warp]);
    else                           acc = run_chunk<false, false>(xw, yw, row0, lane, sstage[warp]);

#pragma unroll
    for (int off = 16; off; off >>= 1)
        acc += __shfl_xor_sync(0xffffffffu, acc, off);
    if (lane == 0) s_red[warp] = acc;
    __syncthreads();
    if (threadIdx.x == 0) {
        float ctot = 0.f;
#pragma unroll
        for (int w = 0; w < BLK / 32; w++) ctot += s_red[w];
        atomicAdd(&g_acc, (double)ctot);
        __threadfence();
        int old = atomicAdd(&g_count, 1);
        if (old == NCTA - 1) {
            double total = g_acc;
            out[0] = (float)(1.0 - total * (1.0 / ((double)Bb * Hh * Ww)));
            g_acc = 0.0;
            g_count = 0;
        }
    }
}

extern "C" void kernel_launch(void* const* d_in, const int* in_sizes, int n_in,
                              void* d_out, int out_size) {
    const float* x = (const float*)d_in[0];
    const float* y = (const float*)d_in[1];
    (void)in_sizes; (void)n_in; (void)out_size;
    k_ssim<<<NCTA, BLK>>>(x, y, (float*)d_out);
}